// round 15
// baseline (speedup 1.0000x reference)
#include <cuda_runtime.h>
#include <cooperative_groups.h>
namespace cg = cooperative_groups;

#define NN 100000
#define GRID 592   // 4 CTAs/SM x 148 SMs co-resident

// ---- scratch (static __device__ globals; no allocation) ----
__device__ int    g_deg[NN];       // zero at load; reset each run in phase B
__device__ float  g_dinv[NN];
__device__ float4 g_S[NN];         // init {sx.xyz, dinv}; scatter adds {sx,0}
__device__ float4 g_Q[NN];         // read-only during scatter: {sx.xyz, 0}
__device__ float  g_w[NN];         // layer-2 weights (atomic during scatter)
__device__ float  g_sum16[16];

__global__ void __launch_bounds__(256, 4)
k_fused(const float* __restrict__ x,
        const int* __restrict__ src, const int* __restrict__ dst, int E,
        const float* __restrict__ W1, const float* __restrict__ b1,
        const float* __restrict__ W2, const float* __restrict__ b2,
        float* __restrict__ out) {
    cg::grid_group grid = cg::this_grid();
    int tid    = blockIdx.x * blockDim.x + threadIdx.x;
    int stride = gridDim.x * blockDim.x;
    int half   = E >> 1;
    const int2* src2 = (const int2*)src;
    const int2* dst2 = (const int2*)dst;

    // ---- Phase A: degree histogram over dst ----
    for (int e = tid; e < half; e += stride) {
        int2 d = __ldg(&dst2[e]);
        atomicAdd(&g_deg[d.x], 1);
        atomicAdd(&g_deg[d.y], 1);
    }
    if (tid == 0 && (E & 1)) atomicAdd(&g_deg[dst[E - 1]], 1);
    grid.sync();

    // ---- Phase B: node prep ----
    if (tid < 16) g_sum16[tid] = 0.f;
    for (int v = tid; v < NN; v += stride) {
        float d = rsqrtf((float)(g_deg[v] + 1));
        g_deg[v]  = 0;                   // deterministic across replays
        g_dinv[v] = d;
        g_w[v]    = d;                   // self-loop term
        float sx0 = d * __ldg(&x[3 * v + 0]);
        float sx1 = d * __ldg(&x[3 * v + 1]);
        float sx2 = d * __ldg(&x[3 * v + 2]);
        g_Q[v] = make_float4(sx0, sx1, sx2, 0.f);
        g_S[v] = make_float4(sx0, sx1, sx2, d);   // self-loop pre-included
    }
    grid.sync();

    // ---- Phase C: fused edge scatter (4 random accesses/edge) ----
    for (int e = tid; e < half; e += stride) {
        int2 s = __ldg(&src2[e]);
        int2 d = __ldg(&dst2[e]);
        float4 q0 = __ldg(&g_Q[s.x]);
        float4 q1 = __ldg(&g_Q[s.y]);
        float dd0 = __ldg(&g_dinv[d.x]);
        float dd1 = __ldg(&g_dinv[d.y]);
        asm volatile("red.global.add.v4.f32 [%0], {%1,%2,%3,%4};"
                     :: "l"(&g_S[d.x]), "f"(q0.x), "f"(q0.y), "f"(q0.z), "f"(q0.w)
                     : "memory");
        asm volatile("red.global.add.f32 [%0], %1;"
                     :: "l"(&g_w[s.x]), "f"(dd0)
                     : "memory");
        asm volatile("red.global.add.v4.f32 [%0], {%1,%2,%3,%4};"
                     :: "l"(&g_S[d.y]), "f"(q1.x), "f"(q1.y), "f"(q1.z), "f"(q1.w)
                     : "memory");
        asm volatile("red.global.add.f32 [%0], %1;"
                     :: "l"(&g_w[s.y]), "f"(dd1)
                     : "memory");
    }
    if (tid == 0 && (E & 1)) {
        int ss = src[E - 1], dd = dst[E - 1];
        float4 q = __ldg(&g_Q[ss]);
        float dv = __ldg(&g_dinv[dd]);
        asm volatile("red.global.add.v4.f32 [%0], {%1,%2,%3,%4};"
                     :: "l"(&g_S[dd]), "f"(q.x), "f"(q.y), "f"(q.z), "f"(q.w)
                     : "memory");
        asm volatile("red.global.add.f32 [%0], %1;"
                     :: "l"(&g_w[ss]), "f"(dv)
                     : "memory");
    }
    grid.sync();

    // ---- Phase D: layer1 + layer2 accumulation ----
    {
        float acc[16];
        #pragma unroll
        for (int j = 0; j < 16; j++) acc[j] = 0.f;

        for (int v = tid; v < NN; v += stride) {
            float4 S = g_S[v];           // {agg.xyz (incl. self), dinv}
            float  d = S.w;
            float  wv = g_w[v] * d;
            float a0 = d * S.x;
            float a1 = d * S.y;
            float a2 = d * S.z;
            #pragma unroll
            for (int j = 0; j < 16; j++) {
                float h = __ldg(&b1[j])
                        + a0 * __ldg(&W1[j])
                        + a1 * __ldg(&W1[16 + j])
                        + a2 * __ldg(&W1[32 + j]);
                acc[j] += wv * fmaxf(h, 0.f);
            }
        }

        #pragma unroll
        for (int j = 0; j < 16; j++) {
            #pragma unroll
            for (int o = 16; o > 0; o >>= 1)
                acc[j] += __shfl_down_sync(0xffffffffu, acc[j], o);
        }
        __shared__ float sm[8][16];
        int lane = threadIdx.x & 31, w = threadIdx.x >> 5;
        if (lane == 0) {
            #pragma unroll
            for (int j = 0; j < 16; j++) sm[w][j] = acc[j];
        }
        __syncthreads();
        if (threadIdx.x < 16) {
            float s = 0.f;
            #pragma unroll
            for (int ww = 0; ww < 8; ww++) s += sm[ww][threadIdx.x];
            atomicAdd(&g_sum16[threadIdx.x], s);
        }
    }
    grid.sync();

    // ---- Phase E: final output (block 0) ----
    if (blockIdx.x == 0 && threadIdx.x < 32) {
        int j = threadIdx.x;
        float s = __ldg(&b2[j]);
        const float inv_n = 1.0f / (float)NN;
        #pragma unroll
        for (int k = 0; k < 16; k++)
            s += (g_sum16[k] * inv_n) * __ldg(&W2[k * 32 + j]);
        out[j] = s;
    }
}

// ---------------------------------------------------------------------------
extern "C" void kernel_launch(void* const* d_in, const int* in_sizes, int n_in,
                              void* d_out, int out_size) {
    const float* x   = (const float*)d_in[0];
    const int*   ei  = (const int*)d_in[1];
    const float* W1  = (const float*)d_in[2];
    const float* b1  = (const float*)d_in[3];
    const float* W2  = (const float*)d_in[4];
    const float* b2  = (const float*)d_in[5];
    float*       out = (float*)d_out;

    int E = in_sizes[1] / 2;
    const int* src = ei;
    const int* dst = ei + E;

    cudaLaunchConfig_t cfg = {};
    cfg.gridDim  = dim3(GRID);
    cfg.blockDim = dim3(256);
    cudaLaunchAttribute attr[1];
    attr[0].id = cudaLaunchAttributeCooperative;
    attr[0].val.cooperative = 1;
    cfg.attrs    = attr;
    cfg.numAttrs = 1;
    cudaLaunchKernelEx(&cfg, k_fused, x, src, dst, E, W1, b1, W2, b2, out);
}

// round 16
// speedup vs baseline: 1.3555x; 1.3555x over previous
#include <cuda_runtime.h>

#define NN 100000

// ---- scratch (static __device__ globals; no allocation) ----
__device__ int    g_deg[NN];       // atomic-only during hist; reset each run
__device__ float  g_dinv[NN];      // read-only after node_prep
__device__ float4 g_S[NN];         // init {sx.xyz, dinv}; scatter adds {sx,0}
__device__ float4 g_Q[NN];         // READ-ONLY during scatter: {sx.xyz, 0}
__device__ float  g_w[NN];         // atomic-only during scatter: layer-2 weights
__device__ float  g_sum16[16];     // layer-2 16-dim reduction

// ---------------------------------------------------------------------------
// degree histogram over dst; vectorized int2 index loads
__global__ void k_hist(const int* __restrict__ dst, int E) {
    int i      = blockIdx.x * blockDim.x + threadIdx.x;
    int stride = gridDim.x * blockDim.x;
    int half   = E >> 1;
    const int2* dst2 = (const int2*)dst;
    for (int e = i; e < half; e += stride) {
        int2 d = __ldg(&dst2[e]);
        atomicAdd(&g_deg[d.x], 1);
        atomicAdd(&g_deg[d.y], 1);
    }
    if (i == 0 && (E & 1)) atomicAdd(&g_deg[dst[E - 1]], 1);
}

// per-node: dinv = rsqrt(deg+1); Q = {sx,0}; S = {sx,dinv}; w = dinv; reset deg
__global__ void k_node_prep(const float* __restrict__ x) {
    int v = blockIdx.x * blockDim.x + threadIdx.x;
    if (blockIdx.x == 0 && threadIdx.x < 16) g_sum16[threadIdx.x] = 0.f;
    if (v >= NN) return;
    float d = rsqrtf((float)(g_deg[v] + 1));
    g_deg[v]  = 0;                       // deterministic across graph replays
    g_dinv[v] = d;
    g_w[v]    = d;
    float sx0 = d * x[3 * v + 0];
    float sx1 = d * x[3 * v + 1];
    float sx2 = d * x[3 * v + 2];
    g_Q[v] = make_float4(sx0, sx1, sx2, 0.f);
    g_S[v] = make_float4(sx0, sx1, sx2, d);
}

// fused edge pass, 2 edges/thread, int2 index loads; 4 random wf/edge
__global__ void k_scatter(const int* __restrict__ src,
                          const int* __restrict__ dst, int E) {
    int i      = blockIdx.x * blockDim.x + threadIdx.x;
    int stride = gridDim.x * blockDim.x;
    int half   = E >> 1;
    const int2* src2 = (const int2*)src;
    const int2* dst2 = (const int2*)dst;
    for (int e = i; e < half; e += stride) {
        int2 s = __ldg(&src2[e]);
        int2 d = __ldg(&dst2[e]);
        float4 q0 = __ldg(&g_Q[s.x]);
        float4 q1 = __ldg(&g_Q[s.y]);
        float dd0 = __ldg(&g_dinv[d.x]);
        float dd1 = __ldg(&g_dinv[d.y]);
        asm volatile("red.global.add.v4.f32 [%0], {%1,%2,%3,%4};"
                     :: "l"(&g_S[d.x]), "f"(q0.x), "f"(q0.y), "f"(q0.z), "f"(q0.w)
                     : "memory");
        asm volatile("red.global.add.f32 [%0], %1;"
                     :: "l"(&g_w[s.x]), "f"(dd0)
                     : "memory");
        asm volatile("red.global.add.v4.f32 [%0], {%1,%2,%3,%4};"
                     :: "l"(&g_S[d.y]), "f"(q1.x), "f"(q1.y), "f"(q1.z), "f"(q1.w)
                     : "memory");
        asm volatile("red.global.add.f32 [%0], %1;"
                     :: "l"(&g_w[s.y]), "f"(dd1)
                     : "memory");
    }
    if (i == 0 && (E & 1)) {
        int s = src[E - 1], d = dst[E - 1];
        float4 q = __ldg(&g_Q[s]);
        float dd = __ldg(&g_dinv[d]);
        asm volatile("red.global.add.v4.f32 [%0], {%1,%2,%3,%4};"
                     :: "l"(&g_S[d]), "f"(q.x), "f"(q.y), "f"(q.z), "f"(q.w)
                     : "memory");
        asm volatile("red.global.add.f32 [%0], %1;"
                     :: "l"(&g_w[s]), "f"(dd)
                     : "memory");
    }
}

// layer-1 per-node + layer-2 accumulation; float4 weight loads (16 LDG.128):
//   a = dinv*S.xyz;  h1 = relu(a @ W1 + b1);  sum16 += (w*dinv)*h1
__global__ void k_layer1(const float4* __restrict__ W1v,   // 12 float4 (3 rows x 4)
                         const float4* __restrict__ b1v) { // 4 float4
    int v = blockIdx.x * blockDim.x + threadIdx.x;
    float4 acc[4];
    #pragma unroll
    for (int jj = 0; jj < 4; jj++) acc[jj] = make_float4(0.f, 0.f, 0.f, 0.f);

    if (v < NN) {
        float4 S = g_S[v];               // issue data loads first
        float  wq = g_w[v];
        float  d = S.w;
        float  wv = wq * d;
        float a0 = d * S.x;
        float a1 = d * S.y;
        float a2 = d * S.z;
        #pragma unroll
        for (int jj = 0; jj < 4; jj++) {
            float4 b  = __ldg(&b1v[jj]);
            float4 w0 = __ldg(&W1v[jj]);       // W1 row 0, features 4jj..4jj+3
            float4 w1 = __ldg(&W1v[4 + jj]);   // W1 row 1
            float4 w2 = __ldg(&W1v[8 + jj]);   // W1 row 2
            float h0 = b.x + a0 * w0.x + a1 * w1.x + a2 * w2.x;
            float h1 = b.y + a0 * w0.y + a1 * w1.y + a2 * w2.y;
            float h2 = b.z + a0 * w0.z + a1 * w1.z + a2 * w2.z;
            float h3 = b.w + a0 * w0.w + a1 * w1.w + a2 * w2.w;
            acc[jj].x = wv * fmaxf(h0, 0.f);
            acc[jj].y = wv * fmaxf(h1, 0.f);
            acc[jj].z = wv * fmaxf(h2, 0.f);
            acc[jj].w = wv * fmaxf(h3, 0.f);
        }
    }

    // warp reduce 16 floats, block reduce, one atomic per feature per block
    float* accf = (float*)acc;
    #pragma unroll
    for (int j = 0; j < 16; j++) {
        #pragma unroll
        for (int o = 16; o > 0; o >>= 1)
            accf[j] += __shfl_down_sync(0xffffffffu, accf[j], o);
    }
    __shared__ float sm[8][16];
    int lane = threadIdx.x & 31, w = threadIdx.x >> 5;
    if (lane == 0) {
        #pragma unroll
        for (int j = 0; j < 16; j++) sm[w][j] = accf[j];
    }
    __syncthreads();
    if (threadIdx.x < 16) {
        float s = 0.f;
        #pragma unroll
        for (int ww = 0; ww < 8; ww++) s += sm[ww][threadIdx.x];
        atomicAdd(&g_sum16[threadIdx.x], s);
    }
}

// final: out[j] = (sum16/N) @ W2 + b2
__global__ void k_final(const float* __restrict__ W2, const float* __restrict__ b2,
                        float* __restrict__ out) {
    int j = threadIdx.x;
    if (j >= 32) return;
    float s = __ldg(&b2[j]);
    const float inv_n = 1.0f / (float)NN;
    #pragma unroll
    for (int k = 0; k < 16; k++)
        s += (g_sum16[k] * inv_n) * __ldg(&W2[k * 32 + j]);
    out[j] = s;
}

// ---------------------------------------------------------------------------
extern "C" void kernel_launch(void* const* d_in, const int* in_sizes, int n_in,
                              void* d_out, int out_size) {
    const float* x   = (const float*)d_in[0];
    const int*   ei  = (const int*)d_in[1];
    const float* W1  = (const float*)d_in[2];
    const float* b1  = (const float*)d_in[3];
    const float* W2  = (const float*)d_in[4];
    const float* b2  = (const float*)d_in[5];
    float*       out = (float*)d_out;

    int E = in_sizes[1] / 2;
    const int* src = ei;
    const int* dst = ei + E;

    int nb_nodes = (NN + 255) / 256;
    int nb_half  = ((E / 2) + 255) / 256;
    if (nb_half > 9600) nb_half = 9600;

    k_hist<<<nb_half, 256>>>(dst, E);
    k_node_prep<<<nb_nodes, 256>>>(x);
    k_scatter<<<nb_half, 256>>>(src, dst, E);
    k_layer1<<<nb_nodes, 256>>>((const float4*)W1, (const float4*)b1);
    k_final<<<1, 32>>>(W2, b2, out);
}

// round 17
// speedup vs baseline: 1.3562x; 1.0005x over previous
#include <cuda_runtime.h>

#define NN 100000

// ---- scratch (static __device__ globals; no allocation) ----
__device__ int    g_deg[NN];       // atomic-only during hist; reset each run
__device__ float  g_dinv[NN];      // read-only after node_prep
__device__ float4 g_S[NN];         // init {sx.xyz, dinv}; scatter adds {sx,0}
__device__ float4 g_Q[NN];         // READ-ONLY during scatter: {sx.xyz, 0}
__device__ float  g_w[NN];         // atomic-only during scatter: layer-2 weights
__device__ float  g_sum16[16];     // layer-2 16-dim reduction

// ---------------------------------------------------------------------------
// degree histogram over dst; vectorized int2 index loads
__global__ void k_hist(const int* __restrict__ dst, int E) {
    int i      = blockIdx.x * blockDim.x + threadIdx.x;
    int stride = gridDim.x * blockDim.x;
    int half   = E >> 1;
    const int2* dst2 = (const int2*)dst;
    for (int e = i; e < half; e += stride) {
        int2 d = __ldg(&dst2[e]);
        atomicAdd(&g_deg[d.x], 1);
        atomicAdd(&g_deg[d.y], 1);
    }
    if (i == 0 && (E & 1)) atomicAdd(&g_deg[dst[E - 1]], 1);
}

// per-node: dinv = rsqrt(deg+1); Q = {sx,0}; S = {sx,dinv}; w = dinv; reset deg
__global__ void k_node_prep(const float* __restrict__ x) {
    int v = blockIdx.x * blockDim.x + threadIdx.x;
    if (blockIdx.x == 0 && threadIdx.x < 16) g_sum16[threadIdx.x] = 0.f;
    if (v >= NN) return;
    float d = rsqrtf((float)(g_deg[v] + 1));
    g_deg[v]  = 0;                       // deterministic across graph replays
    g_dinv[v] = d;
    g_w[v]    = d;
    float sx0 = d * x[3 * v + 0];
    float sx1 = d * x[3 * v + 1];
    float sx2 = d * x[3 * v + 2];
    g_Q[v] = make_float4(sx0, sx1, sx2, 0.f);
    g_S[v] = make_float4(sx0, sx1, sx2, d);
}

// fused edge pass, 2 edges/thread, int2 index loads; 4 random lanes/edge
__global__ void k_scatter(const int* __restrict__ src,
                          const int* __restrict__ dst, int E) {
    int i      = blockIdx.x * blockDim.x + threadIdx.x;
    int stride = gridDim.x * blockDim.x;
    int half   = E >> 1;
    const int2* src2 = (const int2*)src;
    const int2* dst2 = (const int2*)dst;
    for (int e = i; e < half; e += stride) {
        int2 s = __ldg(&src2[e]);
        int2 d = __ldg(&dst2[e]);
        float4 q0 = __ldg(&g_Q[s.x]);
        float4 q1 = __ldg(&g_Q[s.y]);
        float dd0 = __ldg(&g_dinv[d.x]);
        float dd1 = __ldg(&g_dinv[d.y]);
        asm volatile("red.global.add.v4.f32 [%0], {%1,%2,%3,%4};"
                     :: "l"(&g_S[d.x]), "f"(q0.x), "f"(q0.y), "f"(q0.z), "f"(q0.w)
                     : "memory");
        asm volatile("red.global.add.f32 [%0], %1;"
                     :: "l"(&g_w[s.x]), "f"(dd0)
                     : "memory");
        asm volatile("red.global.add.v4.f32 [%0], {%1,%2,%3,%4};"
                     :: "l"(&g_S[d.y]), "f"(q1.x), "f"(q1.y), "f"(q1.z), "f"(q1.w)
                     : "memory");
        asm volatile("red.global.add.f32 [%0], %1;"
                     :: "l"(&g_w[s.y]), "f"(dd1)
                     : "memory");
    }
    if (i == 0 && (E & 1)) {
        int s = src[E - 1], d = dst[E - 1];
        float4 q = __ldg(&g_Q[s]);
        float dd = __ldg(&g_dinv[d]);
        asm volatile("red.global.add.v4.f32 [%0], {%1,%2,%3,%4};"
                     :: "l"(&g_S[d]), "f"(q.x), "f"(q.y), "f"(q.z), "f"(q.w)
                     : "memory");
        asm volatile("red.global.add.f32 [%0], %1;"
                     :: "l"(&g_w[s]), "f"(dd)
                     : "memory");
    }
}

// layer-1 per-node + layer-2 accumulation; float4 weight loads;
// NEW: shallow reduction (1 shfl fold + smem transpose 2-stage) instead of 80-SHFL tree
__global__ void k_layer1(const float4* __restrict__ W1v,   // 12 float4 (3 rows x 4)
                         const float4* __restrict__ b1v) { // 4 float4
    int v = blockIdx.x * blockDim.x + threadIdx.x;
    float4 acc[4];
    #pragma unroll
    for (int jj = 0; jj < 4; jj++) acc[jj] = make_float4(0.f, 0.f, 0.f, 0.f);

    if (v < NN) {
        float4 S = g_S[v];               // issue data loads first
        float  wq = g_w[v];
        float  d = S.w;
        float  wv = wq * d;
        float a0 = d * S.x;
        float a1 = d * S.y;
        float a2 = d * S.z;
        #pragma unroll
        for (int jj = 0; jj < 4; jj++) {
            float4 b  = __ldg(&b1v[jj]);
            float4 w0 = __ldg(&W1v[jj]);
            float4 w1 = __ldg(&W1v[4 + jj]);
            float4 w2 = __ldg(&W1v[8 + jj]);
            float h0 = b.x + a0 * w0.x + a1 * w1.x + a2 * w2.x;
            float h1 = b.y + a0 * w0.y + a1 * w1.y + a2 * w2.y;
            float h2 = b.z + a0 * w0.z + a1 * w1.z + a2 * w2.z;
            float h3 = b.w + a0 * w0.w + a1 * w1.w + a2 * w2.w;
            acc[jj].x = wv * fmaxf(h0, 0.f);
            acc[jj].y = wv * fmaxf(h1, 0.f);
            acc[jj].z = wv * fmaxf(h2, 0.f);
            acc[jj].w = wv * fmaxf(h3, 0.f);
        }
    }

    float* accf = (float*)acc;
    // stage 0: single shfl fold (upper half-warp onto lower) — 16 shfls, 1 level
    #pragma unroll
    for (int j = 0; j < 16; j++)
        accf[j] += __shfl_down_sync(0xffffffffu, accf[j], 16);

    // stage 1: lanes 0-15 of each warp dump 16 floats to smem (128 rows x 16 cols)
    __shared__ float sm[128 * 17];
    __shared__ float sm2[16][17];
    int lane = threadIdx.x & 31, w = threadIdx.x >> 5;
    if (lane < 16) {
        int row = w * 16 + lane;
        #pragma unroll
        for (int j = 0; j < 16; j++) sm[row * 17 + j] = accf[j];
    }
    __syncthreads();

    // stage 2: 256 threads: feature j = tid&15, chunk g = tid>>4 sums 8 rows
    {
        int j = threadIdx.x & 15, g = threadIdx.x >> 4;
        float p = 0.f;
        #pragma unroll
        for (int r = 0; r < 8; r++) p += sm[(g * 8 + r) * 17 + j];
        sm2[g][j] = p;
    }
    __syncthreads();

    // stage 3: threads 0-15 sum 16 partials, one global atomic per feature
    if (threadIdx.x < 16) {
        float s = 0.f;
        #pragma unroll
        for (int g = 0; g < 16; g++) s += sm2[g][threadIdx.x];
        atomicAdd(&g_sum16[threadIdx.x], s);
    }
}

// final: out[j] = (sum16/N) @ W2 + b2
__global__ void k_final(const float* __restrict__ W2, const float* __restrict__ b2,
                        float* __restrict__ out) {
    int j = threadIdx.x;
    if (j >= 32) return;
    float s = __ldg(&b2[j]);
    const float inv_n = 1.0f / (float)NN;
    #pragma unroll
    for (int k = 0; k < 16; k++)
        s += (g_sum16[k] * inv_n) * __ldg(&W2[k * 32 + j]);
    out[j] = s;
}

// ---------------------------------------------------------------------------
extern "C" void kernel_launch(void* const* d_in, const int* in_sizes, int n_in,
                              void* d_out, int out_size) {
    const float* x   = (const float*)d_in[0];
    const int*   ei  = (const int*)d_in[1];
    const float* W1  = (const float*)d_in[2];
    const float* b1  = (const float*)d_in[3];
    const float* W2  = (const float*)d_in[4];
    const float* b2  = (const float*)d_in[5];
    float*       out = (float*)d_out;

    int E = in_sizes[1] / 2;
    const int* src = ei;
    const int* dst = ei + E;

    int nb_nodes = (NN + 255) / 256;
    int nb_half  = ((E / 2) + 255) / 256;
    if (nb_half > 9600) nb_half = 9600;

    k_hist<<<nb_half, 256>>>(dst, E);
    k_node_prep<<<nb_nodes, 256>>>(x);
    k_scatter<<<nb_half, 256>>>(src, dst, E);
    k_layer1<<<nb_nodes, 256>>>((const float4*)W1, (const float4*)b1);
    k_final<<<1, 32>>>(W2, b2, out);
}